// round 15
// baseline (speedup 1.0000x reference)
#include <cuda_runtime.h>
#include <cuda_fp16.h>
#include <math_constants.h>
#include <cstdint>

#define CD 1024
#define ND 1024
#define OD 2048
#define KNN 20

// ---------------- scratch ----------------
__device__ __align__(16) __half g_xh[ND * CD];   // fp16 hi of x^T
__device__ __align__(16) __half g_xl[ND * CD];   // fp16 lo of x^T
__device__ __align__(16) __half g_zh[ND * CD];   // fp16 ((1+eps)*x)^T
__device__ __align__(16) __half g_wh[OD * CD];
__device__ __align__(16) __half g_hh[ND * CD];
__device__ __align__(16) float  g_gram[ND * ND];
__device__ __align__(16) float  g_x2[ND];

// ---------------- helpers ----------------
__device__ __forceinline__ void split_h(float x, __half& h, __half& l) {
    h = __float2half_rn(x);
    l = __float2half_rn(x - __half2float(h));
}
__device__ __forceinline__ uint32_t pack2(__half a, __half b) {
    __half2 t = __halves2half2(a, b);
    return *(uint32_t*)&t;
}
__device__ __forceinline__ uint32_t s2u(const void* p) {
    uint32_t a;
    asm("{ .reg .u64 t; cvta.to.shared.u64 t, %1; cvt.u32.u64 %0, t; }" : "=r"(a) : "l"(p));
    return a;
}
__device__ __forceinline__ void cp16(uint32_t s, const void* g) {
    asm volatile("cp.async.cg.shared.global [%0], [%1], 16;" :: "r"(s), "l"(g));
}
#define CP_COMMIT() asm volatile("cp.async.commit_group;" ::: "memory")
#define CP_WAIT(n)  asm volatile("cp.async.wait_group %0;" :: "n"(n) : "memory")

__device__ __forceinline__ void ldm_x4(uint32_t* r, uint32_t addr) {
    asm volatile("ldmatrix.sync.aligned.m8n8.x4.shared.b16 {%0,%1,%2,%3}, [%4];"
                 : "=r"(r[0]), "=r"(r[1]), "=r"(r[2]), "=r"(r[3]) : "r"(addr));
}
__device__ __forceinline__ void mma_f16(float4& c, const uint32_t* a, const uint32_t* b) {
    asm volatile(
        "mma.sync.aligned.m16n8k16.row.col.f32.f16.f16.f32 "
        "{%0,%1,%2,%3}, {%4,%5,%6,%7}, {%8,%9}, {%0,%1,%2,%3};"
        : "+f"(c.x), "+f"(c.y), "+f"(c.z), "+f"(c.w)
        : "r"(a[0]), "r"(a[1]), "r"(a[2]), "r"(a[3]), "r"(b[0]), "r"(b[1]));
}
// swizzled byte offset for row r (64B rows), 16B chunk c
__device__ __forceinline__ uint32_t swoff(int r, int c) {
    return (uint32_t)(r * 64 + ((c ^ ((r >> 1) & 3)) << 4));
}
// monotonic float -> uint key (ascending)
__device__ __forceinline__ uint32_t fkey(float f) {
    uint32_t b = __float_as_uint(f);
    return b ^ ((uint32_t)(((int32_t)b) >> 31) | 0x80000000u);
}

// ============ split-fp16 GEMM: 256 thr, cp.async x3, ldmatrix ================
// D[M,N] = A[M,K]*B[N,K]^T. PASSES: 3 = AhBh+AlBh+AhBl, 1 = AhBh.
// SYMM: triangular 64-tile grid; off-diag CTAs also write transposed tile.
template <int MTILE, int NT, int WNC, int PASSES, bool SYMM>
__global__ __launch_bounds__(256)
void mma_gemm(const __half* __restrict__ Ah_, const __half* __restrict__ Al_,
              const __half* __restrict__ Bh_, const __half* __restrict__ Bl_,
              float* __restrict__ D, int ldd, float* __restrict__ X2) {
    constexpr int WMC   = 8 / WNC;
    constexpr int MT    = MTILE / (WMC * 16);
    constexpr int NTN   = NT / (WNC * 8);          // even (paired x4 B loads)
    constexpr int ABY   = MTILE * 64;
    constexpr int NA    = (PASSES >= 2) ? 2 : 1;
    constexpr int NB    = (PASSES == 3) ? 2 : 1;
    constexpr int BOFF  = NA * ABY;
    constexpr int BBY   = NT * 64;
    constexpr int STAGE = BOFF + NB * BBY;
    constexpr int NI    = CD / 32;

    extern __shared__ char smem[];
    const uint32_t smb = s2u(smem);

    const int t = threadIdx.x, wid = t >> 5, lane = t & 31;
    const int wm = (wid / WNC) * (MTILE / WMC);
    const int wn = (wid % WNC) * (NT / WNC);
    const int lq = lane & 3, lg = lane >> 2;

    int m0, n0;
    if (SYMM) {
        int b = blockIdx.x, ti = 0;
        while (b >= 16 - ti) { b -= 16 - ti; ti++; }
        m0 = ti * 64; n0 = (ti + b) * 64;
    } else {
        m0 = blockIdx.y * MTILE; n0 = blockIdx.x * NT;
    }

    const int rA = t >> 2, cA = t & 3;

    auto load_stage = [&](int chunk, int st) {
        const uint32_t sb = smb + st * STAGE;
        const size_t kofs = (size_t)chunk * 32;
#pragma unroll
        for (int j = 0; j < MTILE / 64; j++) {
            int r = rA + j * 64;
            uint32_t dst = sb + swoff(r, cA);
            const size_t go = (size_t)(m0 + r) * CD + kofs + cA * 8;
            cp16(dst, Ah_ + go);
            if (PASSES >= 2) cp16(dst + ABY, Al_ + go);
        }
#pragma unroll
        for (int j = 0; j < NT / 64; j++) {
            int r = rA + j * 64;
            uint32_t dst = sb + BOFF + swoff(r, cA);
            const size_t go = (size_t)(n0 + r) * CD + kofs + cA * 8;
            cp16(dst, Bh_ + go);
            if (PASSES == 3) cp16(dst + BBY, Bl_ + go);
        }
    };

    float4 c[MT][NTN];
#pragma unroll
    for (int mt = 0; mt < MT; mt++)
#pragma unroll
        for (int nt = 0; nt < NTN; nt++) c[mt][nt] = make_float4(0.f, 0.f, 0.f, 0.f);

    load_stage(0, 0); CP_COMMIT();
    load_stage(1, 1); CP_COMMIT();

    const int arow = lane & 15;
    const int acsel = lane >> 4;
    const int brow = (lane & 7) + ((lane >> 4) << 3);
    const int bcsel = (lane >> 3) & 1;

    for (int i = 0; i < NI; i++) {
        CP_WAIT(1);
        __syncthreads();
        if (i + 2 < NI) load_stage(i + 2, (i + 2) % 3);
        CP_COMMIT();

        const uint32_t sb = smb + (i % 3) * STAGE;
#pragma unroll
        for (int kb = 0; kb < 2; kb++) {
            uint32_t ah[MT][4], bh[2 * NTN];
#pragma unroll
            for (int mt = 0; mt < MT; mt++)
                ldm_x4(ah[mt], sb + swoff(wm + mt * 16 + arow, 2 * kb + acsel));
#pragma unroll
            for (int np = 0; np < NTN / 2; np++)
                ldm_x4(&bh[np * 4],
                       sb + BOFF + swoff(wn + np * 16 + brow, 2 * kb + bcsel));
#pragma unroll
            for (int mt = 0; mt < MT; mt++)
#pragma unroll
                for (int nt = 0; nt < NTN; nt++)
                    mma_f16(c[mt][nt], ah[mt], &bh[nt * 2]);
            if (PASSES >= 2) {
                uint32_t al[MT][4];
#pragma unroll
                for (int mt = 0; mt < MT; mt++)
                    ldm_x4(al[mt], sb + ABY + swoff(wm + mt * 16 + arow, 2 * kb + acsel));
#pragma unroll
                for (int mt = 0; mt < MT; mt++)
#pragma unroll
                    for (int nt = 0; nt < NTN; nt++)
                        mma_f16(c[mt][nt], al[mt], &bh[nt * 2]);
            }
            if (PASSES == 3) {
                uint32_t bl[2 * NTN];
#pragma unroll
                for (int np = 0; np < NTN / 2; np++)
                    ldm_x4(&bl[np * 4],
                           sb + BOFF + BBY + swoff(wn + np * 16 + brow, 2 * kb + bcsel));
#pragma unroll
                for (int mt = 0; mt < MT; mt++)
#pragma unroll
                    for (int nt = 0; nt < NTN; nt++)
                        mma_f16(c[mt][nt], ah[mt], &bl[nt * 2]);
            }
        }
    }

    // ---- epilogue: direct writes (+ diag extraction) ----
#pragma unroll
    for (int mt = 0; mt < MT; mt++) {
        int r0 = m0 + wm + mt * 16 + lg;
#pragma unroll
        for (int nt = 0; nt < NTN; nt++) {
            int cb = n0 + wn + nt * 8 + lq * 2;
            *(float2*)&D[(size_t)r0 * ldd + cb]       = make_float2(c[mt][nt].x, c[mt][nt].y);
            *(float2*)&D[(size_t)(r0 + 8) * ldd + cb] = make_float2(c[mt][nt].z, c[mt][nt].w);
            if (X2) {
                if (r0 == cb)          X2[r0] = c[mt][nt].x;
                else if (r0 == cb + 1) X2[r0] = c[mt][nt].y;
                if (r0 + 8 == cb)          X2[r0 + 8] = c[mt][nt].z;
                else if (r0 + 8 == cb + 1) X2[r0 + 8] = c[mt][nt].w;
            }
        }
    }

    // ---- mirror for symmetric off-diagonal tiles ----
    if (SYMM && m0 != n0) {
        __syncthreads();
        float* st = (float*)smem;   // [64][65]
#pragma unroll
        for (int mt = 0; mt < MT; mt++) {
            int lm = wm + mt * 16 + lg;
#pragma unroll
            for (int nt = 0; nt < NTN; nt++) {
                int ln = wn + nt * 8 + lq * 2;
                st[lm * 65 + ln]           = c[mt][nt].x;
                st[lm * 65 + ln + 1]       = c[mt][nt].y;
                st[(lm + 8) * 65 + ln]     = c[mt][nt].z;
                st[(lm + 8) * 65 + ln + 1] = c[mt][nt].w;
            }
        }
        __syncthreads();
        const int rr = t >> 2, q = t & 3;
#pragma unroll
        for (int s = 0; s < 4; s++) {
            int cc = q * 16 + s * 4;
            float4 v = make_float4(st[(cc + 0) * 65 + rr], st[(cc + 1) * 65 + rr],
                                   st[(cc + 2) * 65 + rr], st[(cc + 3) * 65 + rr]);
            *(float4*)&D[(size_t)(n0 + rr) * ldd + m0 + cc] = v;
        }
    }
}

// ====== prep: transpose+eps-fold (CTAs 0..255) + W->fp16 (CTAs 256..2303) =====
__global__ __launch_bounds__(256) void prep_kernel(
    const float* __restrict__ x, const float* __restrict__ e,
    const float* __restrict__ W,
    __half* __restrict__ xh, __half* __restrict__ xl, __half* __restrict__ zh,
    __half* __restrict__ wh) {
    const int t = threadIdx.x;
    if (blockIdx.x >= 256) {
        int i = (blockIdx.x - 256) * 256 + t;
        float4 v = ((const float4*)W)[i];
        ((uint2*)wh)[i] = make_uint2(
            pack2(__float2half_rn(v.x), __float2half_rn(v.y)),
            pack2(__float2half_rn(v.z), __float2half_rn(v.w)));
        return;
    }
    __shared__ float tx[32][132];
    __shared__ float tz[32][132];
    const int n0 = (blockIdx.x & 7) * 128;
    const int c0 = (blockIdx.x >> 3) * 32;
    const int lane = t & 31, ty = t >> 5;

#pragma unroll
    for (int j = 0; j < 4; j++) {
        const int r = j * 8 + ty;
        const size_t go = (size_t)(c0 + r) * ND + n0 + lane * 4;
        float4 xv = *(const float4*)&x[go];
        float4 ev = *(const float4*)&e[go];
        float4 zv;
        zv.x = fmaf(ev.x, xv.x, xv.x);
        zv.y = fmaf(ev.y, xv.y, xv.y);
        zv.z = fmaf(ev.z, xv.z, xv.z);
        zv.w = fmaf(ev.w, xv.w, xv.w);
        *(float4*)&tx[r][lane * 4] = xv;
        *(float4*)&tz[r][lane * 4] = zv;
    }
    __syncthreads();

    const int rr = t >> 1;
    const int cb = (t & 1) * 16;
    __half hx[16], lx[16], hz[16];
#pragma unroll
    for (int i = 0; i < 16; i++) {
        split_h(tx[cb + i][rr], hx[i], lx[i]);
        hz[i] = __float2half_rn(tz[cb + i][rr]);
    }
    const size_t o = ((size_t)(n0 + rr) * CD + c0 + cb) / 4;
#pragma unroll
    for (int q = 0; q < 4; q++) {
        ((uint2*)xh)[o + q] = make_uint2(pack2(hx[4*q], hx[4*q+1]), pack2(hx[4*q+2], hx[4*q+3]));
        ((uint2*)xl)[o + q] = make_uint2(pack2(lx[4*q], lx[4*q+1]), pack2(lx[4*q+2], lx[4*q+3]));
        ((uint2*)zh)[o + q] = make_uint2(pack2(hz[4*q], hz[4*q+1]), pack2(hz[4*q+2], hz[4*q+3]));
    }
}

// ========== fused top-20 + gather: 256 thr, 8 rows/block, no idx gmem =========
// Phase 1: warps 0..7 each run REDUX top-20 for one row, indices -> smem.
// Phase 2: all 256 threads gather hh = fp16(zh + sum xh[nb]) for the 8 rows.
__global__ __launch_bounds__(256) void topk_gather_kernel(
    const float* __restrict__ G, const float* __restrict__ x2,
    const __half* __restrict__ xh, const __half* __restrict__ zh,
    __half* __restrict__ hh) {
    __shared__ float d[8][ND];          // 32 KB
    __shared__ int   nbs[8][KNN];
    const int t = threadIdx.x, wid = t >> 5, lane = t & 31;
    const int row = blockIdx.x * 8 + wid;
    const float x2i = x2[row];
    float* dr = d[wid];

    float mv[8];
    int   mi[8];
#pragma unroll
    for (int j = 0; j < 8; j++) {
        const int gi = j * 128 + lane * 4;
        float4 g = *(const float4*)&G[(size_t)row * ND + gi];
        float4 q = *(const float4*)&x2[gi];
        float v0 = 2.f * g.x - x2i - q.x;
        float v1 = 2.f * g.y - x2i - q.y;
        float v2 = 2.f * g.z - x2i - q.z;
        float v3 = 2.f * g.w - x2i - q.w;
        *(float4*)&dr[gi] = make_float4(v0, v1, v2, v3);
        float bv = v0; int bi = gi;
        if (v1 > bv) { bv = v1; bi = gi + 1; }
        if (v2 > bv) { bv = v2; bi = gi + 2; }
        if (v3 > bv) { bv = v3; bi = gi + 3; }
        mv[j] = bv; mi[j] = bi;
    }
    float bv = mv[0]; int bi = mi[0];
#pragma unroll
    for (int j = 1; j < 8; j++)
        if (mv[j] > bv) { bv = mv[j]; bi = mi[j]; }
    __syncwarp();

    for (int k = 0; k < KNN; k++) {
        uint32_t uk = fkey(bv);
        uint32_t M  = __reduce_max_sync(0xffffffffu, uk);
        uint32_t cq = (uk == M) ? (uint32_t)bi : 0xffffffffu;
        uint32_t ci = __reduce_min_sync(0xffffffffu, cq);
        if (lane == 0) nbs[wid][k] = (int)ci;
        if ((uint32_t)bi == ci) {
            dr[ci] = -CUDART_INF_F;
            const int jj = (int)(ci >> 7);
            const int gb = (int)(ci & ~3u);
            float4 v = *(const float4*)&dr[gb];
            float nv = v.x; int ni = gb;
            if (v.y > nv) { nv = v.y; ni = gb + 1; }
            if (v.z > nv) { nv = v.z; ni = gb + 2; }
            if (v.w > nv) { nv = v.w; ni = gb + 3; }
#pragma unroll
            for (int j = 0; j < 8; j++)
                if (j == jj) { mv[j] = nv; mi[j] = ni; }
            bv = mv[0]; bi = mi[0];
#pragma unroll
            for (int j = 1; j < 8; j++)
                if (mv[j] > bv) { bv = mv[j]; bi = mi[j]; }
        }
        __syncwarp();
    }
    __syncthreads();

    // ---- phase 2: gather 8 rows x 256 uint2 chunks ----
    const uint2* xp = (const uint2*)xh;
    const uint2* zp = (const uint2*)zh;
#pragma unroll
    for (int j = 0; j < 8; j++) {
        const int u  = t + j * 256;
        const int lr = u >> 8;            // 0..7
        const int c4 = u & 255;
        const int rw = blockIdx.x * 8 + lr;
        uint2 zv = zp[(size_t)rw * (CD / 4) + c4];
        float2 a0 = __half22float2(*(__half2*)&zv.x);
        float2 a1 = __half22float2(*(__half2*)&zv.y);
        float s0 = a0.x, s1 = a0.y, s2 = a1.x, s3 = a1.y;
        const int* nb = nbs[lr];
#pragma unroll
        for (int k = 0; k < KNN; k++) {
            uint2 v = xp[(size_t)nb[k] * (CD / 4) + c4];
            float2 b0 = __half22float2(*(__half2*)&v.x);
            float2 b1 = __half22float2(*(__half2*)&v.y);
            s0 += b0.x; s1 += b0.y; s2 += b1.x; s3 += b1.y;
        }
        ((uint2*)hh)[(size_t)rw * (CD / 4) + c4] = make_uint2(
            pack2(__float2half_rn(s0), __float2half_rn(s1)),
            pack2(__float2half_rn(s2), __float2half_rn(s3)));
    }
}

// ================= launch =================
extern "C" void kernel_launch(void* const* d_in, const int* in_sizes, int n_in,
                              void* d_out, int out_size) {
    const float* x   = (const float*)d_in[0];   // (C, N)
    const float* W   = (const float*)d_in[1];   // (O, C)
    const float* eps = (const float*)d_in[2];   // (C, N)
    float* out = (float*)d_out;                 // (O, N)

    __half* xh;   cudaGetSymbolAddress((void**)&xh,   g_xh);
    __half* xl;   cudaGetSymbolAddress((void**)&xl,   g_xl);
    __half* zh;   cudaGetSymbolAddress((void**)&zh,   g_zh);
    __half* wh;   cudaGetSymbolAddress((void**)&wh,   g_wh);
    __half* hh;   cudaGetSymbolAddress((void**)&hh,   g_hh);
    float*  gram; cudaGetSymbolAddress((void**)&gram, g_gram);
    float*  x2;   cudaGetSymbolAddress((void**)&x2,   g_x2);

    const int SMEM = 3 * 16384;
    cudaFuncSetAttribute(mma_gemm<64, 64, 4, 3, true>,
                         cudaFuncAttributeMaxDynamicSharedMemorySize, SMEM);
    cudaFuncSetAttribute(mma_gemm<128, 128, 4, 1, false>,
                         cudaFuncAttributeMaxDynamicSharedMemorySize, SMEM);

    // prep: 256 transpose CTAs + 2048 wsplit CTAs
    prep_kernel<<<256 + (OD * CD / 4) / 256, 256>>>(x, eps, W, xh, xl, zh, wh);
    // Gram: symmetric upper-triangle 64x64 tiles: 136 CTAs, 3-pass, diag fused
    mma_gemm<64, 64, 4, 3, true><<<136, 256, SMEM>>>(xh, xl, xh, xl, gram, ND, x2);
    // fused top-20 + neighbor gather: 128 CTAs x 256 thr
    topk_gather_kernel<<<ND / 8, 256>>>(gram, x2, xh, zh, hh);
    // Out: plain fp16 1-pass, CTA 128x128 -> 128 CTAs
    mma_gemm<128, 128, 4, 1, false><<<dim3(ND / 128, OD / 128), 256, SMEM>>>(
        wh, nullptr, hh, nullptr, out, ND, nullptr);
}

// round 16
// speedup vs baseline: 1.0759x; 1.0759x over previous
#include <cuda_runtime.h>
#include <cuda_fp16.h>
#include <math_constants.h>
#include <cstdint>

#define CD 1024
#define ND 1024
#define OD 2048
#define KNN 20

// ---------------- scratch ----------------
__device__ __align__(16) __half g_xh[ND * CD];   // fp16 hi of x^T
__device__ __align__(16) __half g_xl[ND * CD];   // fp16 lo of x^T
__device__ __align__(16) __half g_zh[ND * CD];   // fp16 ((1+eps)*x)^T
__device__ __align__(16) __half g_wh[OD * CD];
__device__ __align__(16) __half g_hh[ND * CD];
__device__ __align__(16) float  g_gram[ND * ND];
__device__ __align__(16) float  g_x2[ND];

// ---------------- helpers ----------------
__device__ __forceinline__ void split_h(float x, __half& h, __half& l) {
    h = __float2half_rn(x);
    l = __float2half_rn(x - __half2float(h));
}
__device__ __forceinline__ uint32_t pack2(__half a, __half b) {
    __half2 t = __halves2half2(a, b);
    return *(uint32_t*)&t;
}
__device__ __forceinline__ uint32_t s2u(const void* p) {
    uint32_t a;
    asm("{ .reg .u64 t; cvta.to.shared.u64 t, %1; cvt.u32.u64 %0, t; }" : "=r"(a) : "l"(p));
    return a;
}
__device__ __forceinline__ void cp16(uint32_t s, const void* g) {
    asm volatile("cp.async.cg.shared.global [%0], [%1], 16;" :: "r"(s), "l"(g));
}
#define CP_COMMIT() asm volatile("cp.async.commit_group;" ::: "memory")
#define CP_WAIT(n)  asm volatile("cp.async.wait_group %0;" :: "n"(n) : "memory")

__device__ __forceinline__ void ldm_x4(uint32_t* r, uint32_t addr) {
    asm volatile("ldmatrix.sync.aligned.m8n8.x4.shared.b16 {%0,%1,%2,%3}, [%4];"
                 : "=r"(r[0]), "=r"(r[1]), "=r"(r[2]), "=r"(r[3]) : "r"(addr));
}
__device__ __forceinline__ void mma_f16(float4& c, const uint32_t* a, const uint32_t* b) {
    asm volatile(
        "mma.sync.aligned.m16n8k16.row.col.f32.f16.f16.f32 "
        "{%0,%1,%2,%3}, {%4,%5,%6,%7}, {%8,%9}, {%0,%1,%2,%3};"
        : "+f"(c.x), "+f"(c.y), "+f"(c.z), "+f"(c.w)
        : "r"(a[0]), "r"(a[1]), "r"(a[2]), "r"(a[3]), "r"(b[0]), "r"(b[1]));
}
// swizzled byte offset: 128B rows (8 x 16B chunks), XOR with row&7
__device__ __forceinline__ uint32_t swoff(int r, int c) {
    return (uint32_t)(r * 128 + ((c ^ (r & 7)) << 4));
}
// monotonic float -> uint key (ascending)
__device__ __forceinline__ uint32_t fkey(float f) {
    uint32_t b = __float_as_uint(f);
    return b ^ ((uint32_t)(((int32_t)b) >> 31) | 0x80000000u);
}

// ============ split-fp16 GEMM: 256 thr, cp.async x3, ldmatrix, K-chunk 64 =====
// D[M,N] = A[M,K]*B[N,K]^T. PASSES: 3 = AhBh+AlBh+AhBl, 1 = AhBh.
// SYMM: triangular 64-tile grid; off-diag CTAs also write transposed tile.
// Stage rows are 128B (64 halves of K); 16 K-iterations, 1 barrier each.
template <int MTILE, int NT, int WNC, int PASSES, bool SYMM>
__global__ __launch_bounds__(256)
void mma_gemm(const __half* __restrict__ Ah_, const __half* __restrict__ Al_,
              const __half* __restrict__ Bh_, const __half* __restrict__ Bl_,
              float* __restrict__ D, int ldd, float* __restrict__ X2) {
    constexpr int WMC   = 8 / WNC;
    constexpr int MT    = MTILE / (WMC * 16);
    constexpr int NTN   = NT / (WNC * 8);          // even (paired x4 B loads)
    constexpr int ABY   = MTILE * 128;
    constexpr int NA    = (PASSES >= 2) ? 2 : 1;
    constexpr int NB    = (PASSES == 3) ? 2 : 1;
    constexpr int BOFF  = NA * ABY;
    constexpr int BBY   = NT * 128;
    constexpr int STAGE = BOFF + NB * BBY;
    constexpr int NI    = CD / 64;

    extern __shared__ char smem[];
    const uint32_t smb = s2u(smem);

    const int t = threadIdx.x, wid = t >> 5, lane = t & 31;
    const int wm = (wid / WNC) * (MTILE / WMC);
    const int wn = (wid % WNC) * (NT / WNC);
    const int lq = lane & 3, lg = lane >> 2;

    int m0, n0;
    if (SYMM) {
        int b = blockIdx.x, ti = 0;
        while (b >= 16 - ti) { b -= 16 - ti; ti++; }
        m0 = ti * 64; n0 = (ti + b) * 64;
    } else {
        m0 = blockIdx.y * MTILE; n0 = blockIdx.x * NT;
    }

    const int rA = t >> 3, cA = t & 7;             // rA 0..31, cA 0..7

    auto load_stage = [&](int chunk, int st) {
        const uint32_t sb = smb + st * STAGE;
        const size_t kofs = (size_t)chunk * 64;
#pragma unroll
        for (int j = 0; j < MTILE / 32; j++) {
            int r = rA + j * 32;
            uint32_t dst = sb + swoff(r, cA);
            const size_t go = (size_t)(m0 + r) * CD + kofs + cA * 8;
            cp16(dst, Ah_ + go);
            if (PASSES >= 2) cp16(dst + ABY, Al_ + go);
        }
#pragma unroll
        for (int j = 0; j < NT / 32; j++) {
            int r = rA + j * 32;
            uint32_t dst = sb + BOFF + swoff(r, cA);
            const size_t go = (size_t)(n0 + r) * CD + kofs + cA * 8;
            cp16(dst, Bh_ + go);
            if (PASSES == 3) cp16(dst + BBY, Bl_ + go);
        }
    };

    float4 c[MT][NTN];
#pragma unroll
    for (int mt = 0; mt < MT; mt++)
#pragma unroll
        for (int nt = 0; nt < NTN; nt++) c[mt][nt] = make_float4(0.f, 0.f, 0.f, 0.f);

    load_stage(0, 0); CP_COMMIT();
    load_stage(1, 1); CP_COMMIT();

    const int arow = lane & 15;
    const int acsel = lane >> 4;
    const int brow = (lane & 7) + ((lane >> 4) << 3);
    const int bcsel = (lane >> 3) & 1;

    for (int i = 0; i < NI; i++) {
        CP_WAIT(1);
        __syncthreads();
        if (i + 2 < NI) load_stage(i + 2, (i + 2) % 3);
        CP_COMMIT();

        const uint32_t sb = smb + (i % 3) * STAGE;
#pragma unroll
        for (int kb = 0; kb < 4; kb++) {
            uint32_t ah[MT][4], bh[2 * NTN];
#pragma unroll
            for (int mt = 0; mt < MT; mt++)
                ldm_x4(ah[mt], sb + swoff(wm + mt * 16 + arow, 2 * kb + acsel));
#pragma unroll
            for (int np = 0; np < NTN / 2; np++)
                ldm_x4(&bh[np * 4],
                       sb + BOFF + swoff(wn + np * 16 + brow, 2 * kb + bcsel));
#pragma unroll
            for (int mt = 0; mt < MT; mt++)
#pragma unroll
                for (int nt = 0; nt < NTN; nt++)
                    mma_f16(c[mt][nt], ah[mt], &bh[nt * 2]);
            if (PASSES >= 2) {
                uint32_t al[MT][4];
#pragma unroll
                for (int mt = 0; mt < MT; mt++)
                    ldm_x4(al[mt], sb + ABY + swoff(wm + mt * 16 + arow, 2 * kb + acsel));
#pragma unroll
                for (int mt = 0; mt < MT; mt++)
#pragma unroll
                    for (int nt = 0; nt < NTN; nt++)
                        mma_f16(c[mt][nt], al[mt], &bh[nt * 2]);
            }
            if (PASSES == 3) {
                uint32_t bl[2 * NTN];
#pragma unroll
                for (int np = 0; np < NTN / 2; np++)
                    ldm_x4(&bl[np * 4],
                           sb + BOFF + BBY + swoff(wn + np * 16 + brow, 2 * kb + bcsel));
#pragma unroll
                for (int mt = 0; mt < MT; mt++)
#pragma unroll
                    for (int nt = 0; nt < NTN; nt++)
                        mma_f16(c[mt][nt], ah[mt], &bl[nt * 2]);
            }
        }
    }

    // ---- epilogue: direct writes (+ diag extraction) ----
#pragma unroll
    for (int mt = 0; mt < MT; mt++) {
        int r0 = m0 + wm + mt * 16 + lg;
#pragma unroll
        for (int nt = 0; nt < NTN; nt++) {
            int cb = n0 + wn + nt * 8 + lq * 2;
            *(float2*)&D[(size_t)r0 * ldd + cb]       = make_float2(c[mt][nt].x, c[mt][nt].y);
            *(float2*)&D[(size_t)(r0 + 8) * ldd + cb] = make_float2(c[mt][nt].z, c[mt][nt].w);
            if (X2) {
                if (r0 == cb)          X2[r0] = c[mt][nt].x;
                else if (r0 == cb + 1) X2[r0] = c[mt][nt].y;
                if (r0 + 8 == cb)          X2[r0 + 8] = c[mt][nt].z;
                else if (r0 + 8 == cb + 1) X2[r0 + 8] = c[mt][nt].w;
            }
        }
    }

    // ---- mirror for symmetric off-diagonal tiles ----
    if (SYMM && m0 != n0) {
        __syncthreads();
        float* st = (float*)smem;   // [64][65]
#pragma unroll
        for (int mt = 0; mt < MT; mt++) {
            int lm = wm + mt * 16 + lg;
#pragma unroll
            for (int nt = 0; nt < NTN; nt++) {
                int ln = wn + nt * 8 + lq * 2;
                st[lm * 65 + ln]           = c[mt][nt].x;
                st[lm * 65 + ln + 1]       = c[mt][nt].y;
                st[(lm + 8) * 65 + ln]     = c[mt][nt].z;
                st[(lm + 8) * 65 + ln + 1] = c[mt][nt].w;
            }
        }
        __syncthreads();
        const int rr = t >> 2, q = t & 3;
#pragma unroll
        for (int s = 0; s < 4; s++) {
            int cc = q * 16 + s * 4;
            float4 v = make_float4(st[(cc + 0) * 65 + rr], st[(cc + 1) * 65 + rr],
                                   st[(cc + 2) * 65 + rr], st[(cc + 3) * 65 + rr]);
            *(float4*)&D[(size_t)(n0 + rr) * ldd + m0 + cc] = v;
        }
    }
}

// ====== prep: transpose + eps-fold only (wsplit moved into topk launch) =======
__global__ __launch_bounds__(256) void prep_kernel(
    const float* __restrict__ x, const float* __restrict__ e,
    __half* __restrict__ xh, __half* __restrict__ xl, __half* __restrict__ zh) {
    __shared__ float tx[32][132];
    __shared__ float tz[32][132];
    const int n0 = (blockIdx.x & 7) * 128;
    const int c0 = (blockIdx.x >> 3) * 32;
    const int t = threadIdx.x;
    const int lane = t & 31, ty = t >> 5;

#pragma unroll
    for (int j = 0; j < 4; j++) {
        const int r = j * 8 + ty;
        const size_t go = (size_t)(c0 + r) * ND + n0 + lane * 4;
        float4 xv = *(const float4*)&x[go];
        float4 ev = *(const float4*)&e[go];
        float4 zv;
        zv.x = fmaf(ev.x, xv.x, xv.x);
        zv.y = fmaf(ev.y, xv.y, xv.y);
        zv.z = fmaf(ev.z, xv.z, xv.z);
        zv.w = fmaf(ev.w, xv.w, xv.w);
        *(float4*)&tx[r][lane * 4] = xv;
        *(float4*)&tz[r][lane * 4] = zv;
    }
    __syncthreads();

    const int rr = t >> 1;
    const int cb = (t & 1) * 16;
    __half hx[16], lx[16], hz[16];
#pragma unroll
    for (int i = 0; i < 16; i++) {
        split_h(tx[cb + i][rr], hx[i], lx[i]);
        hz[i] = __float2half_rn(tz[cb + i][rr]);
    }
    const size_t o = ((size_t)(n0 + rr) * CD + c0 + cb) / 4;
#pragma unroll
    for (int q = 0; q < 4; q++) {
        ((uint2*)xh)[o + q] = make_uint2(pack2(hx[4*q], hx[4*q+1]), pack2(hx[4*q+2], hx[4*q+3]));
        ((uint2*)xl)[o + q] = make_uint2(pack2(lx[4*q], lx[4*q+1]), pack2(lx[4*q+2], lx[4*q+3]));
        ((uint2*)zh)[o + q] = make_uint2(pack2(hz[4*q], hz[4*q+1]), pack2(hz[4*q+2], hz[4*q+3]));
    }
}

// ========== fused top-20 + gather (blocks 0..127) + W-split (128..2175) =======
// Phase 1: warps 0..7 each run REDUX top-20 for one row, indices -> smem.
// Phase 2: all 256 threads gather hh = fp16(zh + sum xh[nb]) for the 8 rows.
// Blocks >= 128: W -> fp16 conversion (overlaps with topk on idle SMs/tail).
__global__ __launch_bounds__(256) void topk_gather_kernel(
    const float* __restrict__ G, const float* __restrict__ x2,
    const __half* __restrict__ xh, const __half* __restrict__ zh,
    __half* __restrict__ hh,
    const float* __restrict__ W, __half* __restrict__ wh) {
    const int t = threadIdx.x;
    if (blockIdx.x >= 128) {
        int i = (blockIdx.x - 128) * 256 + t;
        float4 v = ((const float4*)W)[i];
        ((uint2*)wh)[i] = make_uint2(
            pack2(__float2half_rn(v.x), __float2half_rn(v.y)),
            pack2(__float2half_rn(v.z), __float2half_rn(v.w)));
        return;
    }
    __shared__ float d[8][ND];          // 32 KB
    __shared__ int   nbs[8][KNN];
    const int wid = t >> 5, lane = t & 31;
    const int row = blockIdx.x * 8 + wid;
    const float x2i = x2[row];
    float* dr = d[wid];

    float mv[8];
    int   mi[8];
#pragma unroll
    for (int j = 0; j < 8; j++) {
        const int gi = j * 128 + lane * 4;
        float4 g = *(const float4*)&G[(size_t)row * ND + gi];
        float4 q = *(const float4*)&x2[gi];
        float v0 = 2.f * g.x - x2i - q.x;
        float v1 = 2.f * g.y - x2i - q.y;
        float v2 = 2.f * g.z - x2i - q.z;
        float v3 = 2.f * g.w - x2i - q.w;
        *(float4*)&dr[gi] = make_float4(v0, v1, v2, v3);
        float bv = v0; int bi = gi;
        if (v1 > bv) { bv = v1; bi = gi + 1; }
        if (v2 > bv) { bv = v2; bi = gi + 2; }
        if (v3 > bv) { bv = v3; bi = gi + 3; }
        mv[j] = bv; mi[j] = bi;
    }
    float bv = mv[0]; int bi = mi[0];
#pragma unroll
    for (int j = 1; j < 8; j++)
        if (mv[j] > bv) { bv = mv[j]; bi = mi[j]; }
    __syncwarp();

    for (int k = 0; k < KNN; k++) {
        uint32_t uk = fkey(bv);
        uint32_t M  = __reduce_max_sync(0xffffffffu, uk);
        uint32_t cq = (uk == M) ? (uint32_t)bi : 0xffffffffu;
        uint32_t ci = __reduce_min_sync(0xffffffffu, cq);
        if (lane == 0) nbs[wid][k] = (int)ci;
        if ((uint32_t)bi == ci) {
            dr[ci] = -CUDART_INF_F;
            const int jj = (int)(ci >> 7);
            const int gb = (int)(ci & ~3u);
            float4 v = *(const float4*)&dr[gb];
            float nv = v.x; int ni = gb;
            if (v.y > nv) { nv = v.y; ni = gb + 1; }
            if (v.z > nv) { nv = v.z; ni = gb + 2; }
            if (v.w > nv) { nv = v.w; ni = gb + 3; }
#pragma unroll
            for (int j = 0; j < 8; j++)
                if (j == jj) { mv[j] = nv; mi[j] = ni; }
            bv = mv[0]; bi = mi[0];
#pragma unroll
            for (int j = 1; j < 8; j++)
                if (mv[j] > bv) { bv = mv[j]; bi = mi[j]; }
        }
        __syncwarp();
    }
    __syncthreads();

    // ---- phase 2: gather 8 rows x 256 uint2 chunks ----
    const uint2* xp = (const uint2*)xh;
    const uint2* zp = (const uint2*)zh;
#pragma unroll
    for (int j = 0; j < 8; j++) {
        const int u  = t + j * 256;
        const int lr = u >> 8;            // 0..7
        const int c4 = u & 255;
        const int rw = blockIdx.x * 8 + lr;
        uint2 zv = zp[(size_t)rw * (CD / 4) + c4];
        float2 a0 = __half22float2(*(__half2*)&zv.x);
        float2 a1 = __half22float2(*(__half2*)&zv.y);
        float s0 = a0.x, s1 = a0.y, s2 = a1.x, s3 = a1.y;
        const int* nb = nbs[lr];
#pragma unroll
        for (int k = 0; k < KNN; k++) {
            uint2 v = xp[(size_t)nb[k] * (CD / 4) + c4];
            float2 b0 = __half22float2(*(__half2*)&v.x);
            float2 b1 = __half22float2(*(__half2*)&v.y);
            s0 += b0.x; s1 += b0.y; s2 += b1.x; s3 += b1.y;
        }
        ((uint2*)hh)[(size_t)rw * (CD / 4) + c4] = make_uint2(
            pack2(__float2half_rn(s0), __float2half_rn(s1)),
            pack2(__float2half_rn(s2), __float2half_rn(s3)));
    }
}

// ================= launch =================
extern "C" void kernel_launch(void* const* d_in, const int* in_sizes, int n_in,
                              void* d_out, int out_size) {
    const float* x   = (const float*)d_in[0];   // (C, N)
    const float* W   = (const float*)d_in[1];   // (O, C)
    const float* eps = (const float*)d_in[2];   // (C, N)
    float* out = (float*)d_out;                 // (O, N)

    __half* xh;   cudaGetSymbolAddress((void**)&xh,   g_xh);
    __half* xl;   cudaGetSymbolAddress((void**)&xl,   g_xl);
    __half* zh;   cudaGetSymbolAddress((void**)&zh,   g_zh);
    __half* wh;   cudaGetSymbolAddress((void**)&wh,   g_wh);
    __half* hh;   cudaGetSymbolAddress((void**)&hh,   g_hh);
    float*  gram; cudaGetSymbolAddress((void**)&gram, g_gram);
    float*  x2;   cudaGetSymbolAddress((void**)&x2,   g_x2);

    // gram: MTILE=64,NT=64,PASSES=3 -> stage 2*8192+2*8192 = 32768
    // out:  MTILE=128,NT=128,PASSES=1 -> stage 16384+16384 = 32768
    const int SMEM = 3 * 32768;   // 98304
    cudaFuncSetAttribute(mma_gemm<64, 64, 4, 3, true>,
                         cudaFuncAttributeMaxDynamicSharedMemorySize, SMEM);
    cudaFuncSetAttribute(mma_gemm<128, 128, 4, 1, false>,
                         cudaFuncAttributeMaxDynamicSharedMemorySize, SMEM);

    // prep: transpose + eps-fold (256 CTAs)
    prep_kernel<<<256, 256>>>(x, eps, xh, xl, zh);
    // Gram: symmetric upper-triangle 64x64 tiles: 136 CTAs, 3-pass, diag fused
    mma_gemm<64, 64, 4, 3, true><<<136, 256, SMEM>>>(xh, xl, xh, xl, gram, ND, x2);
    // fused top-20 + gather (128 blocks) + W->fp16 (2048 blocks, overlapped)
    topk_gather_kernel<<<128 + (OD * CD / 4) / 256, 256>>>(gram, x2, xh, zh, hh, W, wh);
    // Out: plain fp16 1-pass, CTA 128x128 -> 128 CTAs, K-chunk 64
    mma_gemm<128, 128, 4, 1, false><<<dim3(ND / 128, OD / 128), 256, SMEM>>>(
        wh, nullptr, hh, nullptr, out, ND, nullptr);
}